// round 6
// baseline (speedup 1.0000x reference)
#include <cuda_runtime.h>
#include <cstdint>
#include <cstddef>

typedef unsigned long long u64;

#define TT 512
#define BB 64
#define II 512
#define HH 512
#define G4 2048
#define NCTA 128
#define NTH 256

// ---- device-global scratch (allocation-free) ----
__device__ __align__(16) float g_xp[(size_t)TT * G4 * BB];   // [t][gate_row][b]
__device__ __align__(16) float g_hb2[2][BB][HH];             // h double buffer, [b][hid]
__device__ unsigned int g_cnt[8];                            // per-chunk monotonic counters

// ---- helpers ----
__device__ __forceinline__ u64 dup2f(float x) {
    u64 r; asm("mov.b64 %0, {%1, %1};" : "=l"(r) : "f"(x)); return r;
}
__device__ __forceinline__ void fma2(u64 &d, u64 a, u64 b) {
    asm("fma.rn.f32x2 %0, %1, %2, %0;" : "+l"(d) : "l"(a), "l"(b));
}
__device__ __forceinline__ void cp16(uint32_t s, const void* g) {
    asm volatile("cp.async.cg.shared.global [%0], [%1], 16;" :: "r"(s), "l"(g));
}
__device__ __forceinline__ void cpcommit() { asm volatile("cp.async.commit_group;"); }
template<int N> __device__ __forceinline__ void cpwait() {
    asm volatile("cp.async.wait_group %0;" :: "n"(N));
}
__device__ __forceinline__ float sigm(float x) { return 1.0f / (1.0f + __expf(-x)); }

// ============================================================
// Kernel 1: x_proj[t][g][b] = x @ W_ih^T + b_ih + b_hh
// GEMM M=32768 (t*64+b), N=2048, K=512. 128x128 tile, 8x8 micro, FFMA2.
// (unchanged from R4 except counter reset)
// ============================================================
__global__ void __launch_bounds__(256, 2) k1_gemm(
    const float* __restrict__ x, const float* __restrict__ Wih,
    const float* __restrict__ bih, const float* __restrict__ bhh)
{
    __shared__ float sm[8704 + 128];
    float* As   = sm;          // [16][136]
    float* Bs   = sm + 2176;   // [16][136]
    float* stage = sm;         // [128 n][68] overlay after compute
    float* bias = sm + 8704;   // [128]

    const int tid = threadIdx.x;
    const int m0 = blockIdx.x * 128;
    const int n0 = blockIdx.y * 128;
    if (blockIdx.x == 0 && blockIdx.y == 0 && tid < 8) g_cnt[tid] = 0u;  // reset sync counters

    if (tid < 128) bias[tid] = bih[n0 + tid] + bhh[n0 + tid];

    const int tx = tid & 15;   // n-dir
    const int ty = tid >> 4;   // m-dir

    u64 acc[8][4];
    #pragma unroll
    for (int i = 0; i < 8; i++)
        #pragma unroll
        for (int j = 0; j < 4; j++) acc[i][j] = 0ull;

    const int lr = tid >> 2;   // load row (0..63), +64 for second
    const int cq = tid & 3;    // which float4 of the 16-wide k tile

    for (int kt = 0; kt < 512; kt += 16) {
        __syncthreads();
        #pragma unroll
        for (int h = 0; h < 2; h++) {
            int r = lr + h * 64;
            float4 v = *(const float4*)(x + (size_t)(m0 + r) * II + kt + cq * 4);
            As[(cq*4+0)*136 + r] = v.x; As[(cq*4+1)*136 + r] = v.y;
            As[(cq*4+2)*136 + r] = v.z; As[(cq*4+3)*136 + r] = v.w;
            float4 w = *(const float4*)(Wih + (size_t)(n0 + r) * II + kt + cq * 4);
            Bs[(cq*4+0)*136 + r] = w.x; Bs[(cq*4+1)*136 + r] = w.y;
            Bs[(cq*4+2)*136 + r] = w.z; Bs[(cq*4+3)*136 + r] = w.w;
        }
        __syncthreads();
        #pragma unroll
        for (int k = 0; k < 16; k++) {
            float4 al = *(const float4*)(As + k*136 + ty*8);
            float4 ah = *(const float4*)(As + k*136 + ty*8 + 4);
            float4 bl = *(const float4*)(Bs + k*136 + tx*8);
            float4 bh = *(const float4*)(Bs + k*136 + tx*8 + 4);
            u64 bp0 = ((const u64*)&bl)[0], bp1 = ((const u64*)&bl)[1];
            u64 bp2 = ((const u64*)&bh)[0], bp3 = ((const u64*)&bh)[1];
            float av[8] = {al.x, al.y, al.z, al.w, ah.x, ah.y, ah.z, ah.w};
            #pragma unroll
            for (int i = 0; i < 8; i++) {
                u64 ad = dup2f(av[i]);
                fma2(acc[i][0], ad, bp0); fma2(acc[i][1], ad, bp1);
                fma2(acc[i][2], ad, bp2); fma2(acc[i][3], ad, bp3);
            }
        }
    }

    // Tile covers 2 timesteps (m = t*64 + b). Stage [n][b], write coalesced.
    const int t0 = m0 >> 6;
    #pragma unroll
    for (int half = 0; half < 2; half++) {
        __syncthreads();
        if ((ty >> 3) == half) {
            int mb = (ty & 7) * 8;  // b within half
            #pragma unroll
            for (int i = 0; i < 8; i++) {
                #pragma unroll
                for (int j = 0; j < 4; j++) {
                    float2 v = *(float2*)&acc[i][j];
                    stage[(tx*8 + 2*j    )*68 + mb + i] = v.x;
                    stage[(tx*8 + 2*j + 1)*68 + mb + i] = v.y;
                }
            }
        }
        __syncthreads();
        float* obase = g_xp + ((size_t)(t0 + half) * G4 + n0) * BB;
        #pragma unroll
        for (int q = 0; q < 8; q++) {
            int e4 = tid + q * 256;      // 0..2047 float4s
            int nn = e4 >> 4;            // 0..127
            int b4 = (e4 & 15) * 4;
            float4 v = *(const float4*)(stage + nn*68 + b4);
            float bs = bias[nn];
            v.x += bs; v.y += bs; v.z += bs; v.w += bs;
            *(float4*)(obase + nn * BB + b4) = v;
        }
    }
}

// ============================================================
// Kernel 2: persistent recurrence. 128 CTAs x 256 thr, single wave.
// CTA owns 4 hidden units (16 gate rows). W_hh slice in smem all 512 steps.
// h is [b][k]; FFMA2 pairs adjacent k (no dup movs). Fine-grained per-chunk
// counters instead of a full grid barrier.
// ============================================================
__global__ void __launch_bounds__(NTH, 1) k2_rec(
    const float* __restrict__ Whh, float* __restrict__ out)
{
    extern __shared__ float sm2[];
    float* Ws = sm2;                    // [16][520]
    float* hs = sm2 + 16 * 520;         // [4 buf][64 b][68]
    float* gs = hs + 4 * 64 * 68;       // [16][68]

    const int tid = threadIdx.x;
    const int cta = blockIdx.x;
    const int H0 = cta * 4;
    const int myck = cta >> 4;          // chunk this CTA produces

    // Load W_hh rows: local row r = q*4+u  ->  global row q*512 + H0 + u
    for (int i = tid; i < 16 * 128; i += NTH) {
        int r = i >> 7;
        int k4 = i & 127;
        int q = r >> 2, u = r & 3;
        float4 v = *(const float4*)(Whh + (size_t)(q * 512 + H0 + u) * HH + k4 * 4);
        float* d = Ws + r * 520 + k4 * 4;
        d[0] = v.x; d[1] = v.y; d[2] = v.z; d[3] = v.w;
    }
    __syncthreads();

    const int r   = tid >> 4;           // gate row 0..15
    const int b0  = (tid & 15) * 4;     // 4 batches per thread
    const int lane = tid & 31;
    const uint32_t hs_s = (uint32_t)__cvta_generic_to_shared(hs);

    float cst[4] = {0.f, 0.f, 0.f, 0.f};   // cell state (gate threads tid<64)

    for (int t = 0; t < TT; t++) {
        u64 acc[4][2];
        #pragma unroll
        for (int j2 = 0; j2 < 4; j2++) { acc[j2][0] = 0ull; acc[j2][1] = 0ull; }

        if (t > 0) {
            const float* hsrc = &g_hb2[(t - 1) & 1][0][0];
            const unsigned tgt = (unsigned)t * 16u;

            auto P = [&](int j) {
                int ck = (myck + j) & 7;
                if (lane == 0) {
                    unsigned v;
                    do {
                        asm volatile("ld.global.acquire.gpu.u32 %0, [%1];"
                                     : "=r"(v) : "l"(g_cnt + ck));
                    } while (v < tgt);
                }
                __syncwarp();
                uint32_t dst = hs_s + (uint32_t)((j & 3) * 64 * 68 * 4);
                const float* src = hsrc + ck * 64;
                #pragma unroll
                for (int w = 0; w < 4; w++) {
                    int f = tid + w * NTH;        // 0..1023
                    int row = f >> 4;
                    int col = (f & 15) * 4;
                    cp16(dst + (uint32_t)(row * 68 + col) * 4u,
                         src + (size_t)row * HH + col);
                }
                cpcommit();
            };

            P(0); P(1);
            for (int j = 0; j < 8; j++) {
                if (j < 7) cpwait<1>(); else cpwait<0>();
                __syncthreads();
                int ck = (myck + j) & 7;
                const float* hb = hs + (j & 3) * 64 * 68 + b0 * 68;
                const float* wp = Ws + r * 520 + ck * 64;
                #pragma unroll
                for (int kk = 0; kk < 64; kk += 4) {
                    float4 w4 = *(const float4*)(wp + kk);
                    u64 w01 = ((const u64*)&w4)[0];
                    u64 w23 = ((const u64*)&w4)[1];
                    #pragma unroll
                    for (int j2 = 0; j2 < 4; j2++) {
                        float4 h4 = *(const float4*)(hb + j2 * 68 + kk);
                        fma2(acc[j2][0], w01, ((const u64*)&h4)[0]);
                        fma2(acc[j2][1], w23, ((const u64*)&h4)[1]);
                    }
                }
                if (j < 6) { __syncthreads(); P(j + 2); }
            }
        }

        // reduce lane pairs, stage sums gs[row][b]
        {
            float4 s;
            float2 e0 = *(float2*)&acc[0][0], f0 = *(float2*)&acc[0][1];
            float2 e1 = *(float2*)&acc[1][0], f1 = *(float2*)&acc[1][1];
            float2 e2 = *(float2*)&acc[2][0], f2 = *(float2*)&acc[2][1];
            float2 e3 = *(float2*)&acc[3][0], f3 = *(float2*)&acc[3][1];
            s.x = (e0.x + e0.y) + (f0.x + f0.y);
            s.y = (e1.x + e1.y) + (f1.x + f1.y);
            s.z = (e2.x + e2.y) + (f2.x + f2.y);
            s.w = (e3.x + e3.y) + (f3.x + f3.y);
            *(float4*)(gs + r * 68 + b0) = s;
        }
        __syncthreads();

        // gate math: thread b (tid<64) handles 4 units
        if (tid < 64) {
            int b = tid;
            const float* xpb = g_xp + (size_t)t * G4 * BB + b;
            float4 hv;
            float* hvp = (float*)&hv;
            #pragma unroll
            for (int u = 0; u < 4; u++) {
                float gi = gs[(0  + u) * 68 + b] + xpb[(size_t)(0    + H0 + u) * BB];
                float gf = gs[(4  + u) * 68 + b] + xpb[(size_t)(512  + H0 + u) * BB];
                float gg = gs[(8  + u) * 68 + b] + xpb[(size_t)(1024 + H0 + u) * BB];
                float go = gs[(12 + u) * 68 + b] + xpb[(size_t)(1536 + H0 + u) * BB];
                float si = sigm(gi), sf = sigm(gf), so = sigm(go);
                float tg = tanhf(gg);
                float c = sf * cst[u] + si * tg;
                cst[u] = c;
                hvp[u] = so * tanhf(c);
            }
            *(float4*)(&g_hb2[t & 1][b][H0]) = hv;
            *(float4*)(out + ((size_t)t * BB + b) * HH + H0) = hv;
        }
        __syncthreads();
        if (tid == 0) {
            __threadfence();
            atomicAdd(&g_cnt[myck], 1u);
        }
        // no trailing barrier: next step's P() polls the counters
    }
}

// ============================================================
extern "C" void kernel_launch(void* const* d_in, const int* in_sizes, int n_in,
                              void* d_out, int out_size)
{
    const float* x   = (const float*)d_in[0];
    const float* Wih = (const float*)d_in[1];
    const float* Whh = (const float*)d_in[2];
    const float* bih = (const float*)d_in[3];
    const float* bhh = (const float*)d_in[4];
    float* out = (float*)d_out;

    dim3 g1(256, 16);
    k1_gemm<<<g1, 256>>>(x, Wih, bih, bhh);

    const int smem2 = (16 * 520 + 4 * 64 * 68 + 16 * 68) * 4;
    cudaFuncSetAttribute(k2_rec, cudaFuncAttributeMaxDynamicSharedMemorySize, smem2);
    k2_rec<<<NCTA, NTH, smem2>>>(Whh, out);
}

// round 7
// speedup vs baseline: 3.9318x; 3.9318x over previous
#include <cuda_runtime.h>
#include <cstdint>
#include <cstddef>

typedef unsigned long long u64;

#define TT 512
#define BB 64
#define II 512
#define HH 512
#define G4 2048
#define NCTA 128
#define NTH 256

// ---- device-global scratch (allocation-free) ----
__device__ __align__(16) float g_xp[(size_t)TT * G4 * BB];   // [t][gate_row][b]
__device__ __align__(16) float g_h[2][BB * HH];              // h double buffer, [b][hid]
__device__ unsigned int g_bar;

// ---- helpers ----
__device__ __forceinline__ u64 dup2f(float x) {
    u64 r; asm("mov.b64 %0, {%1, %1};" : "=l"(r) : "f"(x)); return r;
}
__device__ __forceinline__ void fma2(u64 &d, u64 a, u64 b) {
    asm("fma.rn.f32x2 %0, %1, %2, %0;" : "+l"(d) : "l"(a), "l"(b));
}
__device__ __forceinline__ void cp16(uint32_t s, const void* g) {
    asm volatile("cp.async.cg.shared.global [%0], [%1], 16;" :: "r"(s), "l"(g));
}
__device__ __forceinline__ void cpcommit() { asm volatile("cp.async.commit_group;"); }
template<int N> __device__ __forceinline__ void cpwait() {
    asm volatile("cp.async.wait_group %0;" :: "n"(N));
}
__device__ __forceinline__ float sigm(float x) { return 1.0f / (1.0f + __expf(-x)); }

// ============================================================
// Kernel 1: x_proj[t][g][b] = x @ W_ih^T + b_ih + b_hh
// GEMM M=32768 (t*64+b), N=2048, K=512. 128x128 tile, 8x8 micro, FFMA2.
// (proven in R4/R5; only change: resets g_bar)
// ============================================================
__global__ void __launch_bounds__(256, 2) k1_gemm(
    const float* __restrict__ x, const float* __restrict__ Wih,
    const float* __restrict__ bih, const float* __restrict__ bhh)
{
    __shared__ float sm[8704 + 128];
    float* As   = sm;          // [16][136]
    float* Bs   = sm + 2176;   // [16][136]
    float* stage = sm;         // [128 n][68] overlay after compute
    float* bias = sm + 8704;   // [128]

    const int tid = threadIdx.x;
    const int m0 = blockIdx.x * 128;
    const int n0 = blockIdx.y * 128;
    if (blockIdx.x == 0 && blockIdx.y == 0 && tid == 0) g_bar = 0u;

    if (tid < 128) bias[tid] = bih[n0 + tid] + bhh[n0 + tid];

    const int tx = tid & 15;   // n-dir
    const int ty = tid >> 4;   // m-dir

    u64 acc[8][4];
    #pragma unroll
    for (int i = 0; i < 8; i++)
        #pragma unroll
        for (int j = 0; j < 4; j++) acc[i][j] = 0ull;

    const int lr = tid >> 2;   // load row (0..63), +64 for second
    const int cq = tid & 3;    // which float4 of the 16-wide k tile

    for (int kt = 0; kt < 512; kt += 16) {
        __syncthreads();
        #pragma unroll
        for (int h = 0; h < 2; h++) {
            int r = lr + h * 64;
            float4 v = *(const float4*)(x + (size_t)(m0 + r) * II + kt + cq * 4);
            As[(cq*4+0)*136 + r] = v.x; As[(cq*4+1)*136 + r] = v.y;
            As[(cq*4+2)*136 + r] = v.z; As[(cq*4+3)*136 + r] = v.w;
            float4 w = *(const float4*)(Wih + (size_t)(n0 + r) * II + kt + cq * 4);
            Bs[(cq*4+0)*136 + r] = w.x; Bs[(cq*4+1)*136 + r] = w.y;
            Bs[(cq*4+2)*136 + r] = w.z; Bs[(cq*4+3)*136 + r] = w.w;
        }
        __syncthreads();
        #pragma unroll
        for (int k = 0; k < 16; k++) {
            float4 al = *(const float4*)(As + k*136 + ty*8);
            float4 ah = *(const float4*)(As + k*136 + ty*8 + 4);
            float4 bl = *(const float4*)(Bs + k*136 + tx*8);
            float4 bh = *(const float4*)(Bs + k*136 + tx*8 + 4);
            u64 bp0 = ((const u64*)&bl)[0], bp1 = ((const u64*)&bl)[1];
            u64 bp2 = ((const u64*)&bh)[0], bp3 = ((const u64*)&bh)[1];
            float av[8] = {al.x, al.y, al.z, al.w, ah.x, ah.y, ah.z, ah.w};
            #pragma unroll
            for (int i = 0; i < 8; i++) {
                u64 ad = dup2f(av[i]);
                fma2(acc[i][0], ad, bp0); fma2(acc[i][1], ad, bp1);
                fma2(acc[i][2], ad, bp2); fma2(acc[i][3], ad, bp3);
            }
        }
    }

    const int t0 = m0 >> 6;
    #pragma unroll
    for (int half = 0; half < 2; half++) {
        __syncthreads();
        if ((ty >> 3) == half) {
            int mb = (ty & 7) * 8;
            #pragma unroll
            for (int i = 0; i < 8; i++) {
                #pragma unroll
                for (int j = 0; j < 4; j++) {
                    float2 v = *(float2*)&acc[i][j];
                    stage[(tx*8 + 2*j    )*68 + mb + i] = v.x;
                    stage[(tx*8 + 2*j + 1)*68 + mb + i] = v.y;
                }
            }
        }
        __syncthreads();
        float* obase = g_xp + ((size_t)(t0 + half) * G4 + n0) * BB;
        #pragma unroll
        for (int q = 0; q < 8; q++) {
            int e4 = tid + q * 256;
            int nn = e4 >> 4;
            int b4 = (e4 & 15) * 4;
            float4 v = *(const float4*)(stage + nn*68 + b4);
            float bs = bias[nn];
            v.x += bs; v.y += bs; v.z += bs; v.w += bs;
            *(float4*)(obase + nn * BB + b4) = v;
        }
    }
}

// ============================================================
// Kernel 2: persistent recurrence. 128 CTAs x 256 thr, single wave.
// CTA owns 4 hidden units (16 gate rows, W slice in smem all steps).
// Thread = 16 rows x 1 batch x 16 k  (kq = tid>>6, b = tid&63):
//   - h[b][4k] loaded once per 4k, reused by all 16 rows (min crossbar)
//   - w rows warp-broadcast; both operands k-paired -> pure FFMA2, no dups
// Single global barrier per step: red.release + 1 acquire-poller per CTA.
// ============================================================
__global__ void __launch_bounds__(NTH, 1) k2_rec(
    const float* __restrict__ Whh, float* __restrict__ out)
{
    extern __shared__ float sm2[];
    float* Ws = sm2;                    // [16][520]
    float* hs = sm2 + 16 * 520;         // [4 buf][64 b][68]
    float* gs = hs + 4 * 64 * 68;       // [4 kq][16 row][68]

    const int tid = threadIdx.x;
    const int cta = blockIdx.x;
    const int H0 = cta * 4;

    // Load W_hh rows: local row r = q*4+u  ->  global row q*512 + H0 + u
    for (int i = tid; i < 16 * 128; i += NTH) {
        int r = i >> 7;
        int k4 = i & 127;
        int q = r >> 2, u = r & 3;
        float4 v = *(const float4*)(Whh + (size_t)(q * 512 + H0 + u) * HH + k4 * 4);
        float* d = Ws + r * 520 + k4 * 4;
        d[0] = v.x; d[1] = v.y; d[2] = v.z; d[3] = v.w;
    }
    __syncthreads();

    const int kq = tid >> 6;            // 0..3 : k-slice AND gate-unit
    const int b  = tid & 63;            // batch element
    const uint32_t hs_s = (uint32_t)__cvta_generic_to_shared(hs);

    float cst = 0.0f;                   // cell state for (unit kq, batch b)

    for (int t = 0; t < TT; t++) {
        // prefetch gate inputs (independent of h) -> hides DRAM under sync
        const float* xpb = g_xp + (size_t)t * G4 * BB;
        float xv[4];
        #pragma unroll
        for (int q = 0; q < 4; q++)
            xv[q] = xpb[(size_t)(q * 512 + H0 + kq) * BB + b];

        u64 acc[16];
        #pragma unroll
        for (int rr = 0; rr < 16; rr++) acc[rr] = 0ull;

        if (t > 0) {
            if (tid == 0) {
                unsigned tgt = (unsigned)t * NCTA, v;
                do {
                    asm volatile("ld.global.acquire.gpu.u32 %0, [%1];"
                                 : "=r"(v) : "l"(&g_bar));
                } while (v < tgt);
            }
            __syncthreads();

            const float* hsrc = g_h[(t - 1) & 1];   // [b][hid]

            auto P = [&](int j) {
                int ck = (cta + j) & 7;
                uint32_t dst = hs_s + (uint32_t)((j & 3) * 64 * 68 * 4);
                const float* src = hsrc + ck * 64;
                #pragma unroll
                for (int w = 0; w < 4; w++) {
                    int f = tid + w * NTH;          // 0..1023
                    int row = f >> 4;               // batch row
                    int col = (f & 15) * 4;         // k within chunk
                    cp16(dst + (uint32_t)(row * 68 + col) * 4u,
                         src + (size_t)row * HH + col);
                }
                cpcommit();
            };

            P(0); P(1);
            for (int j = 0; j < 8; j++) {
                if (j < 7) cpwait<1>(); else cpwait<0>();
                __syncthreads();
                const float* hb = hs + (j & 3) * 64 * 68 + b * 68 + kq * 16;
                const float* wp = Ws + ((cta + j) & 7) * 64 + kq * 16;
                #pragma unroll
                for (int g = 0; g < 4; g++) {
                    float4 h4 = *(const float4*)(hb + g * 4);
                    u64 h01 = ((const u64*)&h4)[0];
                    u64 h23 = ((const u64*)&h4)[1];
                    #pragma unroll
                    for (int rr = 0; rr < 16; rr++) {
                        float4 w4 = *(const float4*)(wp + rr * 520 + g * 4);
                        fma2(acc[rr], ((const u64*)&w4)[0], h01);
                        fma2(acc[rr], ((const u64*)&w4)[1], h23);
                    }
                }
                if (j < 6) { __syncthreads(); P(j + 2); }
            }
        }

        // fold k-pairs, stage partials into this kq's plane
        #pragma unroll
        for (int rr = 0; rr < 16; rr++) {
            float2 e = *(float2*)&acc[rr];
            gs[(kq * 16 + rr) * 68 + b] = e.x + e.y;
        }
        __syncthreads();

        // gate math: thread (unit kq, batch b); sum the 4 kq planes
        {
            float gsum[4];
            #pragma unroll
            for (int q = 0; q < 4; q++) {
                int row = q * 4 + kq;
                float s = gs[(0  + row) * 68 + b] + gs[(16 + row) * 68 + b]
                        + gs[(32 + row) * 68 + b] + gs[(48 + row) * 68 + b];
                gsum[q] = xv[q] + s;
            }
            float si = sigm(gsum[0]);
            float sf = sigm(gsum[1]);
            float tg = tanhf(gsum[2]);
            float so = sigm(gsum[3]);
            float c = sf * cst + si * tg;
            cst = c;
            float h = so * tanhf(c);
            g_h[t & 1][(size_t)b * HH + H0 + kq] = h;
            out[((size_t)t * BB + b) * HH + H0 + kq] = h;
        }
        __syncthreads();
        if (tid == 0) {
            __threadfence();
            asm volatile("red.release.gpu.global.add.u32 [%0], %1;"
                         :: "l"(&g_bar), "r"(1u) : "memory");
        }
    }
}

// ============================================================
extern "C" void kernel_launch(void* const* d_in, const int* in_sizes, int n_in,
                              void* d_out, int out_size)
{
    const float* x   = (const float*)d_in[0];
    const float* Wih = (const float*)d_in[1];
    const float* Whh = (const float*)d_in[2];
    const float* bih = (const float*)d_in[3];
    const float* bhh = (const float*)d_in[4];
    float* out = (float*)d_out;

    dim3 g1(256, 16);
    k1_gemm<<<g1, 256>>>(x, Wih, bih, bhh);

    const int smem2 = (16 * 520 + 4 * 64 * 68 + 4 * 16 * 68) * 4;
    cudaFuncSetAttribute(k2_rec, cudaFuncAttributeMaxDynamicSharedMemorySize, smem2);
    k2_rec<<<NCTA, NTH, smem2>>>(Whh, out);
}